// round 4
// baseline (speedup 1.0000x reference)
#include <cuda_runtime.h>
#include <math.h>

#define HH 512
#define WW 512
#define HWSZ (HH * WW)
#define NTHREADS 512
#define NWARPS 16
#define EPSV 1e-8f

__global__ __launch_bounds__(NTHREADS) void ircn_kernel(
    const float* __restrict__ in,
    const float* __restrict__ gRow_p, const float* __restrict__ bRow_p,
    const float* __restrict__ gCol_p, const float* __restrict__ bCol_p,
    const float* __restrict__ gIns_p, const float* __restrict__ bIns_p,
    float* __restrict__ out, int C)
{
    __shared__ __align__(16) float rowS[HH];
    __shared__ __align__(16) float rowSS[HH];
    __shared__ __align__(16) float colS[WW];
    __shared__ __align__(16) float colSS[WW];
    __shared__ float warpRed[NWARPS * 2];
    __shared__ float sIns[2];  // mean, inv

    const int plane = blockIdx.x;      // b*C + c
    const int c = plane % C;
    const int b = plane / C;
    const float* __restrict__ p = in + (size_t)plane * HWSZ;

    const int tid = threadIdx.x;
    const int lane = tid & 31;
    const int wid = tid >> 5;

    // init column accumulators (tid < 512 == WW)
    colS[tid] = 0.f;
    colSS[tid] = 0.f;
    __syncthreads();

    // ---------------- Phase A: stats ----------------
    float cs[16], css[16];
#pragma unroll
    for (int i = 0; i < 16; i++) { cs[i] = 0.f; css[i] = 0.f; }

    for (int r = wid; r < HH; r += NWARPS) {
        const float4* rp = (const float4*)(p + r * WW);
        float s = 0.f, ss = 0.f;
#pragma unroll
        for (int k = 0; k < 4; k++) {
            float4 v = rp[k * 32 + lane];
            s += (v.x + v.y) + (v.z + v.w);
            ss += v.x * v.x + v.y * v.y + v.z * v.z + v.w * v.w;
            cs[k * 4 + 0] += v.x;  css[k * 4 + 0] += v.x * v.x;
            cs[k * 4 + 1] += v.y;  css[k * 4 + 1] += v.y * v.y;
            cs[k * 4 + 2] += v.z;  css[k * 4 + 2] += v.z * v.z;
            cs[k * 4 + 3] += v.w;  css[k * 4 + 3] += v.w * v.w;
        }
#pragma unroll
        for (int o = 16; o > 0; o >>= 1) {
            s += __shfl_xor_sync(0xffffffffu, s, o);
            ss += __shfl_xor_sync(0xffffffffu, ss, o);
        }
        if (lane == 0) { rowS[r] = s; rowSS[r] = ss; }
    }

    // flush per-lane column partials (16 fixed columns per lane)
#pragma unroll
    for (int k = 0; k < 4; k++) {
        int cbase = (k * 32 + lane) * 4;
#pragma unroll
        for (int j = 0; j < 4; j++) {
            atomicAdd(&colS[cbase + j], cs[k * 4 + j]);
            atomicAdd(&colSS[cbase + j], css[k * 4 + j]);
        }
    }
    __syncthreads();

    // plane (instance) reduction from row sums
    {
        float s = rowS[tid], ss = rowSS[tid];
#pragma unroll
        for (int o = 16; o > 0; o >>= 1) {
            s += __shfl_xor_sync(0xffffffffu, s, o);
            ss += __shfl_xor_sync(0xffffffffu, ss, o);
        }
        if (lane == 0) { warpRed[wid] = s; warpRed[NWARPS + wid] = ss; }
    }
    __syncthreads();
    if (tid == 0) {
        float s = 0.f, ss = 0.f;
        for (int i = 0; i < NWARPS; i++) { s += warpRed[i]; ss += warpRed[NWARPS + i]; }
        float m = s * (1.f / HWSZ);
        float v = fmaxf(ss * (1.f / HWSZ) - m * m, 0.f);
        sIns[0] = m;
        sIns[1] = 1.f / (sqrtf(v + EPSV) + EPSV);
    }

    // convert row/col raw sums -> mean & inv (thread t touches only index t; no
    // cross-thread hazard vs the plane reduce, which already read rowS[tid] above)
    {
        float m = rowS[tid] * (1.f / WW);
        float v = fmaxf(rowSS[tid] * (1.f / WW) - m * m, 0.f);
        rowS[tid] = m;
        rowSS[tid] = 1.f / (sqrtf(v + EPSV) + EPSV);

        float mc = colS[tid] * (1.f / HH);
        float vc = fmaxf(colSS[tid] * (1.f / HH) - mc * mc, 0.f);
        colS[tid] = mc;
        colSS[tid] = 1.f / (sqrtf(vc + EPSV) + EPSV);
    }
    __syncthreads();

    // ---------------- Phase B: normalize & write ----------------
    const float gRow = gRow_p[c], bRow = bRow_p[c];
    const float gCol = gCol_p[c], bCol = bCol_p[c];
    const float gIns = gIns_p[c], bIns = bIns_p[c];
    const float insM = sIns[0], insI = sIns[1];

    const size_t outBase = (size_t)b * 3 * C * HWSZ;
    float* __restrict__ oI = out + outBase + (size_t)c * HWSZ;
    float* __restrict__ oR = out + outBase + (size_t)(C + c) * HWSZ;
    float* __restrict__ oC = out + outBase + (size_t)(2 * C + c) * HWSZ;

    const float4* colM4 = (const float4*)colS;
    const float4* colI4 = (const float4*)colSS;

    for (int r = wid; r < HH; r += NWARPS) {
        const float4* rp = (const float4*)(p + r * WW);
        float4* oIp = (float4*)(oI + r * WW);
        float4* oRp = (float4*)(oR + r * WW);
        float4* oCp = (float4*)(oC + r * WW);
        const float rm = rowS[r];
        const float ri = rowSS[r];
#pragma unroll
        for (int k = 0; k < 4; k++) {
            const int idx = k * 32 + lane;
            float4 v = __ldcs(&rp[idx]);
            float4 cm = colM4[idx];
            float4 ci = colI4[idx];
            float4 o;
            // instance norm
            o.x = gIns * (v.x - insM) * insI + bIns;
            o.y = gIns * (v.y - insM) * insI + bIns;
            o.z = gIns * (v.z - insM) * insI + bIns;
            o.w = gIns * (v.w - insM) * insI + bIns;
            __stcs(&oIp[idx], o);
            // row norm
            o.x = gRow * (v.x - rm) * ri + bRow;
            o.y = gRow * (v.y - rm) * ri + bRow;
            o.z = gRow * (v.z - rm) * ri + bRow;
            o.w = gRow * (v.w - rm) * ri + bRow;
            __stcs(&oRp[idx], o);
            // col norm
            o.x = gCol * (v.x - cm.x) * ci.x + bCol;
            o.y = gCol * (v.y - cm.y) * ci.y + bCol;
            o.z = gCol * (v.z - cm.z) * ci.z + bCol;
            o.w = gCol * (v.w - cm.w) * ci.w + bCol;
            __stcs(&oCp[idx], o);
        }
    }
}

extern "C" void kernel_launch(void* const* d_in, const int* in_sizes, int n_in,
                              void* d_out, int out_size) {
    const float* in = (const float*)d_in[0];
    const float* gRow = (const float*)d_in[1];
    const float* bRow = (const float*)d_in[2];
    const float* gCol = (const float*)d_in[3];
    const float* bCol = (const float*)d_in[4];
    const float* gIns = (const float*)d_in[5];
    const float* bIns = (const float*)d_in[6];
    float* out = (float*)d_out;

    const int C = in_sizes[1];                  // 128
    const int nPlanes = in_sizes[0] / HWSZ;     // B*C = 256

    ircn_kernel<<<nPlanes, NTHREADS>>>(in, gRow, bRow, gCol, bCol, gIns, bIns, out, C);
}